// round 1
// baseline (speedup 1.0000x reference)
#include <cuda_runtime.h>
#include <math.h>

// Problem constants (fixed for this dataset entry)
#define E_DIM  1024
#define HID_DIM 4096
#define WSZ 64
#define M_TOK 16384

// Scratch (allocation-free rule: __device__ globals)
__device__ float g_Q [M_TOK * E_DIM];
__device__ float g_K [M_TOK * E_DIM];
__device__ float g_V [M_TOK * E_DIM];
__device__ float g_AT[M_TOK * E_DIM];
__device__ float g_X1[M_TOK * E_DIM];
__device__ float g_H [M_TOK * HID_DIM];
__device__ float g_F [M_TOK * E_DIM];

// ---------------------------------------------------------------------------
// SGEMM: C[M,N] = A[M,K] @ B[K,N] + bias[N]  (optional ReLU)
// 128x128 tile, BK=8, 256 threads, 8x8 per-thread micro-tile.
// ---------------------------------------------------------------------------
template<int RELU>
__global__ __launch_bounds__(256, 2)
void sgemm_bias(const float* __restrict__ A, const float* __restrict__ B,
                const float* __restrict__ bias, float* __restrict__ C,
                int M, int N, int K)
{
    __shared__ float As[8][128];
    __shared__ float Bs[8][128];

    const int tid = threadIdx.x;
    const int bm = blockIdx.y * 128;
    const int bn = blockIdx.x * 128;

    const int aRow = tid >> 1;          // 0..127
    const int aCol = (tid & 1) << 2;    // 0 or 4
    const int bRow = tid >> 5;          // 0..7
    const int bCol = (tid & 31) << 2;   // 0..124

    const int tm = (tid >> 4) << 3;     // 0..120
    const int tn = (tid & 15) << 3;     // 0..120

    const float* Aptr = A + (size_t)(bm + aRow) * K + aCol;
    const float* Bptr = B + (size_t)bRow * N + bn + bCol;

    float acc[8][8];
#pragma unroll
    for (int i = 0; i < 8; i++)
#pragma unroll
        for (int j = 0; j < 8; j++) acc[i][j] = 0.f;

    for (int k0 = 0; k0 < K; k0 += 8) {
        const float4 av = *(const float4*)(Aptr + k0);
        const float4 bv = *(const float4*)(Bptr + (size_t)k0 * N);
        __syncthreads();
        As[aCol + 0][aRow] = av.x;
        As[aCol + 1][aRow] = av.y;
        As[aCol + 2][aRow] = av.z;
        As[aCol + 3][aRow] = av.w;
        *(float4*)&Bs[bRow][bCol] = bv;
        __syncthreads();
#pragma unroll
        for (int k = 0; k < 8; k++) {
            const float4 a0 = *(const float4*)&As[k][tm];
            const float4 a1 = *(const float4*)&As[k][tm + 4];
            const float4 b0 = *(const float4*)&Bs[k][tn];
            const float4 b1 = *(const float4*)&Bs[k][tn + 4];
            const float a[8] = {a0.x, a0.y, a0.z, a0.w, a1.x, a1.y, a1.z, a1.w};
            const float b[8] = {b0.x, b0.y, b0.z, b0.w, b1.x, b1.y, b1.z, b1.w};
#pragma unroll
            for (int i = 0; i < 8; i++)
#pragma unroll
                for (int j = 0; j < 8; j++)
                    acc[i][j] = fmaf(a[i], b[j], acc[i][j]);
        }
    }

#pragma unroll
    for (int i = 0; i < 8; i++) {
        const size_t row = (size_t)(bm + tm + i);
#pragma unroll
        for (int j = 0; j < 8; j += 4) {
            float4 c;
            c.x = acc[i][j + 0] + bias[bn + tn + j + 0];
            c.y = acc[i][j + 1] + bias[bn + tn + j + 1];
            c.z = acc[i][j + 2] + bias[bn + tn + j + 2];
            c.w = acc[i][j + 3] + bias[bn + tn + j + 3];
            if (RELU) {
                c.x = fmaxf(c.x, 0.f); c.y = fmaxf(c.y, 0.f);
                c.z = fmaxf(c.z, 0.f); c.w = fmaxf(c.w, 0.f);
            }
            *(float4*)(C + row * N + bn + tn + j) = c;
        }
    }
}

// ---------------------------------------------------------------------------
// Fused window attention: one block per 64-token window.
// scores = Q Kt * scale -> softmax -> P @ V
// ---------------------------------------------------------------------------
__global__ __launch_bounds__(256, 4)
void window_attn(const float* __restrict__ Q, const float* __restrict__ K,
                 const float* __restrict__ V, float* __restrict__ O)
{
    __shared__ float sA[64 * 33 * 2];   // stage1: Qs|Ks (stride 33); stage2: Vs (stride 66)
    __shared__ float sS[64 * 65];       // scores / probabilities

    const int tid = threadIdx.x;
    const int w = blockIdx.x;
    const float* Qw = Q + (size_t)w * WSZ * E_DIM;
    const float* Kw = K + (size_t)w * WSZ * E_DIM;
    const float* Vw = V + (size_t)w * WSZ * E_DIM;

    float* Qs = sA;
    float* Ks = sA + 64 * 33;

    const int qb = (tid >> 4) << 2;   // 0..60 (query row base)
    const int nb = (tid & 15) << 2;   // 0..60 (key / embed col base)

    float acc[4][4];
#pragma unroll
    for (int i = 0; i < 4; i++)
#pragma unroll
        for (int j = 0; j < 4; j++) acc[i][j] = 0.f;

    // ---- stage 1: scores = Q @ K^T, K-dim streamed in chunks of 32 ----
    for (int c0 = 0; c0 < E_DIM; c0 += 32) {
        __syncthreads();
        for (int i = tid; i < 512; i += 256) {
            const int r = i >> 3;
            const int c4 = (i & 7) << 2;
            const float4 qv = *(const float4*)(Qw + (size_t)r * E_DIM + c0 + c4);
            const float4 kv = *(const float4*)(Kw + (size_t)r * E_DIM + c0 + c4);
            Qs[r * 33 + c4 + 0] = qv.x; Qs[r * 33 + c4 + 1] = qv.y;
            Qs[r * 33 + c4 + 2] = qv.z; Qs[r * 33 + c4 + 3] = qv.w;
            Ks[r * 33 + c4 + 0] = kv.x; Ks[r * 33 + c4 + 1] = kv.y;
            Ks[r * 33 + c4 + 2] = kv.z; Ks[r * 33 + c4 + 3] = kv.w;
        }
        __syncthreads();
#pragma unroll 8
        for (int c = 0; c < 32; c++) {
            float a[4], b[4];
#pragma unroll
            for (int i = 0; i < 4; i++) a[i] = Qs[(qb + i) * 33 + c];
#pragma unroll
            for (int j = 0; j < 4; j++) b[j] = Ks[(nb + j) * 33 + c];
#pragma unroll
            for (int i = 0; i < 4; i++)
#pragma unroll
                for (int j = 0; j < 4; j++)
                    acc[i][j] = fmaf(a[i], b[j], acc[i][j]);
        }
    }

    const float SCALE = 0.03125f;  // 1024^-0.5
#pragma unroll
    for (int i = 0; i < 4; i++)
#pragma unroll
        for (int j = 0; j < 4; j++)
            sS[(qb + i) * 65 + nb + j] = acc[i][j] * SCALE;
    __syncthreads();

    // ---- softmax: 4 threads per row, 16 cols each ----
    {
        const int row = tid >> 2;
        const int part = (tid & 3) << 4;
        float vb[16];
        float m = -1e30f;
#pragma unroll
        for (int j = 0; j < 16; j++) {
            vb[j] = sS[row * 65 + part + j];
            m = fmaxf(m, vb[j]);
        }
        m = fmaxf(m, __shfl_xor_sync(0xffffffffu, m, 1));
        m = fmaxf(m, __shfl_xor_sync(0xffffffffu, m, 2));
        float s = 0.f;
#pragma unroll
        for (int j = 0; j < 16; j++) { vb[j] = __expf(vb[j] - m); s += vb[j]; }
        s += __shfl_xor_sync(0xffffffffu, s, 1);
        s += __shfl_xor_sync(0xffffffffu, s, 2);
        const float inv = 1.f / s;
#pragma unroll
        for (int j = 0; j < 16; j++) sS[row * 65 + part + j] = vb[j] * inv;
    }
    __syncthreads();

    // ---- stage 2: out = P @ V, embed dim streamed in chunks of 64 ----
    float* Vs = sA;  // stride 66, 64x66 = 4224 floats fits the 2*64*33 region
    for (int e0 = 0; e0 < E_DIM; e0 += 64) {
        __syncthreads();
        for (int i = tid; i < 1024; i += 256) {
            const int r = i >> 4;
            const int c4 = (i & 15) << 2;
            const float4 vv = *(const float4*)(Vw + (size_t)r * E_DIM + e0 + c4);
            Vs[r * 66 + c4 + 0] = vv.x; Vs[r * 66 + c4 + 1] = vv.y;
            Vs[r * 66 + c4 + 2] = vv.z; Vs[r * 66 + c4 + 3] = vv.w;
        }
        __syncthreads();
        float o[4][4];
#pragma unroll
        for (int i = 0; i < 4; i++)
#pragma unroll
            for (int j = 0; j < 4; j++) o[i][j] = 0.f;
#pragma unroll 16
        for (int k = 0; k < 64; k++) {
            float p[4], vv[4];
#pragma unroll
            for (int i = 0; i < 4; i++) p[i] = sS[(qb + i) * 65 + k];
#pragma unroll
            for (int j = 0; j < 4; j++) vv[j] = Vs[k * 66 + nb + j];
#pragma unroll
            for (int i = 0; i < 4; i++)
#pragma unroll
                for (int j = 0; j < 4; j++)
                    o[i][j] = fmaf(p[i], vv[j], o[i][j]);
        }
#pragma unroll
        for (int i = 0; i < 4; i++) {
            float4 c = make_float4(o[i][0], o[i][1], o[i][2], o[i][3]);
            *(float4*)(O + (size_t)(w * WSZ + qb + i) * E_DIM + e0 + nb) = c;
        }
    }
}

// ---------------------------------------------------------------------------
// out = LayerNorm(A + B) * g + be     (one block per row of 1024)
// ---------------------------------------------------------------------------
__global__ __launch_bounds__(256)
void add_ln(const float* __restrict__ A, const float* __restrict__ B,
            const float* __restrict__ g, const float* __restrict__ be,
            float* __restrict__ out)
{
    const int row = blockIdx.x;
    const int tid = threadIdx.x;
    const int col = tid << 2;

    const float4 a = *(const float4*)(A + (size_t)row * E_DIM + col);
    const float4 b = *(const float4*)(B + (size_t)row * E_DIM + col);
    float v0 = a.x + b.x, v1 = a.y + b.y, v2 = a.z + b.z, v3 = a.w + b.w;

    float s  = v0 + v1 + v2 + v3;
    float sq = v0 * v0 + v1 * v1 + v2 * v2 + v3 * v3;
#pragma unroll
    for (int o = 16; o > 0; o >>= 1) {
        s  += __shfl_xor_sync(0xffffffffu, s, o);
        sq += __shfl_xor_sync(0xffffffffu, sq, o);
    }
    __shared__ float rs[8], rq[8];
    __shared__ float s_mean, s_rstd;
    if ((tid & 31) == 0) { rs[tid >> 5] = s; rq[tid >> 5] = sq; }
    __syncthreads();
    if (tid == 0) {
        float ts = 0.f, tq = 0.f;
#pragma unroll
        for (int i = 0; i < 8; i++) { ts += rs[i]; tq += rq[i]; }
        const float mean = ts * (1.f / E_DIM);
        const float var = tq * (1.f / E_DIM) - mean * mean;
        s_mean = mean;
        s_rstd = rsqrtf(var + 1e-5f);
    }
    __syncthreads();
    const float mean = s_mean, rstd = s_rstd;

    const float4 gg = *(const float4*)(g + col);
    const float4 bb = *(const float4*)(be + col);
    float4 o4;
    o4.x = (v0 - mean) * rstd * gg.x + bb.x;
    o4.y = (v1 - mean) * rstd * gg.y + bb.y;
    o4.z = (v2 - mean) * rstd * gg.z + bb.z;
    o4.w = (v3 - mean) * rstd * gg.w + bb.w;
    *(float4*)(out + (size_t)row * E_DIM + col) = o4;
}

// ---------------------------------------------------------------------------
extern "C" void kernel_launch(void* const* d_in, const int* in_sizes, int n_in,
                              void* d_out, int out_size)
{
    const float* x   = (const float*)d_in[0];
    const float* Wq  = (const float*)d_in[1];
    const float* bq  = (const float*)d_in[2];
    const float* Wk  = (const float*)d_in[3];
    const float* bk  = (const float*)d_in[4];
    const float* Wv  = (const float*)d_in[5];
    const float* bv  = (const float*)d_in[6];
    const float* g1  = (const float*)d_in[7];
    const float* be1 = (const float*)d_in[8];
    const float* W1  = (const float*)d_in[9];
    const float* b1  = (const float*)d_in[10];
    const float* W2  = (const float*)d_in[11];
    const float* b2  = (const float*)d_in[12];
    const float* g2  = (const float*)d_in[13];
    const float* be2 = (const float*)d_in[14];
    float* out = (float*)d_out;

    const int M = in_sizes[0] / E_DIM;   // 16384

    float *Qp, *Kp, *Vp, *Ap, *X1p, *Hp, *Fp;
    cudaGetSymbolAddress((void**)&Qp,  g_Q);
    cudaGetSymbolAddress((void**)&Kp,  g_K);
    cudaGetSymbolAddress((void**)&Vp,  g_V);
    cudaGetSymbolAddress((void**)&Ap,  g_AT);
    cudaGetSymbolAddress((void**)&X1p, g_X1);
    cudaGetSymbolAddress((void**)&Hp,  g_H);
    cudaGetSymbolAddress((void**)&Fp,  g_F);

    const dim3 blk(256);
    const dim3 gQKV(E_DIM / 128, M / 128);
    sgemm_bias<0><<<gQKV, blk>>>(x, Wq, bq, Qp, M, E_DIM, E_DIM);
    sgemm_bias<0><<<gQKV, blk>>>(x, Wk, bk, Kp, M, E_DIM, E_DIM);
    sgemm_bias<0><<<gQKV, blk>>>(x, Wv, bv, Vp, M, E_DIM, E_DIM);

    window_attn<<<M / WSZ, blk>>>(Qp, Kp, Vp, Ap);

    add_ln<<<M, blk>>>(x, Ap, g1, be1, X1p);

    sgemm_bias<1><<<dim3(HID_DIM / 128, M / 128), blk>>>(X1p, W1, b1, Hp, M, HID_DIM, E_DIM);
    sgemm_bias<0><<<dim3(E_DIM / 128, M / 128), blk>>>(Hp, W2, b2, Fp, M, E_DIM, HID_DIM);

    add_ln<<<M, blk>>>(X1p, Fp, g2, be2, out);
}

// round 3
// speedup vs baseline: 3.3315x; 3.3315x over previous
#include <cuda_runtime.h>
#include <cstdint>
#include <math.h>

// ---------------------------------------------------------------------------
// Problem constants
// ---------------------------------------------------------------------------
#define E_DIM   1024
#define HID_DIM 4096
#define WSZ     64
#define M_TOK   16384

// ---------------------------------------------------------------------------
// Scratch (__device__ globals; no allocation allowed)
// ---------------------------------------------------------------------------
__device__ float g_Q  [M_TOK * E_DIM];
__device__ float g_K  [M_TOK * E_DIM];
__device__ float g_V  [M_TOK * E_DIM];
__device__ float g_AT [M_TOK * E_DIM];
__device__ float g_X1 [M_TOK * E_DIM];
__device__ float g_H  [(size_t)M_TOK * HID_DIM];
__device__ float g_F  [M_TOK * E_DIM];

// ---------------------------------------------------------------------------
// PTX helpers
// ---------------------------------------------------------------------------
__device__ __forceinline__ uint32_t smem_to_u32(const void* p) {
    uint32_t a;
    asm("{ .reg .u64 t; cvta.to.shared.u64 t, %1; cvt.u32.u64 %0, t; }"
        : "=r"(a) : "l"(p));
    return a;
}

#define CP_ASYNC16(saddr, gptr) \
    asm volatile("cp.async.cg.shared.global [%0], [%1], 16;" \
                 :: "r"(saddr), "l"(gptr))
#define CP_COMMIT() asm volatile("cp.async.commit_group;" ::: "memory")
#define CP_WAIT(n)  asm volatile("cp.async.wait_group %0;" :: "n"(n) : "memory")

#define CVT_TF32(x) asm("cvt.rna.tf32.f32 %0, %0;" : "+r"(x))

__device__ __forceinline__ void mma_tf32(float* c, const uint32_t* a, const uint32_t* b) {
    asm volatile(
        "mma.sync.aligned.m16n8k8.row.col.f32.tf32.tf32.f32 "
        "{%0,%1,%2,%3}, {%4,%5,%6,%7}, {%8,%9}, {%0,%1,%2,%3};"
        : "+f"(c[0]), "+f"(c[1]), "+f"(c[2]), "+f"(c[3])
        : "r"(a[0]), "r"(a[1]), "r"(a[2]), "r"(a[3]), "r"(b[0]), "r"(b[1]));
}

// ---------------------------------------------------------------------------
// tf32 tensor-core GEMM: C[M,N] = A[M,K] @ B[K,N] + bias  (optional ReLU)
// 128x128x32 tile, 256 threads (4x2 warps, 32x64 warp tile), cp.async
// double-buffered fp32 smem. A stride 36 floats, B stride 132 floats
// (both make mma fragment LDS conflict-free).
// ---------------------------------------------------------------------------
#define A_STRIDE 36
#define B_STRIDE 132
#define A_TILE_BYTES (128 * A_STRIDE * 4)   // 18432
#define B_TILE_BYTES (32 * B_STRIDE * 4)    // 16896
#define OFF_A0 0
#define OFF_B0 (A_TILE_BYTES)
#define OFF_A1 (A_TILE_BYTES + B_TILE_BYTES)
#define OFF_B1 (2 * A_TILE_BYTES + B_TILE_BYTES)
#define GEMM_SMEM_BYTES (2 * (A_TILE_BYTES + B_TILE_BYTES))  // 70656

template<int RELU>
__global__ __launch_bounds__(256, 2)
void gemm_tf32(const float* __restrict__ A, const float* __restrict__ B,
               const float* __restrict__ bias, float* __restrict__ C,
               int M, int N, int K)
{
    extern __shared__ char smem[];
    const uint32_t sbase = smem_to_u32(smem);
    float* smemf = (float*)smem;

    const int tid = threadIdx.x;
    const int wid = tid >> 5;
    const int lid = tid & 31;
    const int g = lid >> 2;     // group 0..7
    const int t = lid & 3;      // 0..3

    const int wm = wid & 3;     // warp row (4) -> 32 rows each
    const int wn = wid >> 2;    // warp col (2) -> 64 cols each

    const int m0 = blockIdx.y * 128;
    const int n0 = blockIdx.x * 128;

    const float* Ag = A + (size_t)m0 * K;
    const float* Bg = B + n0;

    // cp.async loader for one 128x32 A tile + 32x128 B tile
    auto load_tile = [&](int k0, uint32_t aoff, uint32_t boff) {
#pragma unroll
        for (int i = 0; i < 4; i++) {
            const int idx = tid + i * 256;
            const int r = idx >> 3, c = (idx & 7) << 2;
            CP_ASYNC16(sbase + aoff + (uint32_t)(r * A_STRIDE + c) * 4,
                       Ag + (size_t)r * K + k0 + c);
        }
#pragma unroll
        for (int i = 0; i < 4; i++) {
            const int idx = tid + i * 256;
            const int r = idx >> 5, c = (idx & 31) << 2;
            CP_ASYNC16(sbase + boff + (uint32_t)(r * B_STRIDE + c) * 4,
                       Bg + (size_t)(k0 + r) * N + c);
        }
        CP_COMMIT();
    };

    float acc[2][8][4];
#pragma unroll
    for (int mi = 0; mi < 2; mi++)
#pragma unroll
        for (int ni = 0; ni < 8; ni++)
#pragma unroll
            for (int j = 0; j < 4; j++) acc[mi][ni][j] = 0.f;

    const int NK = K >> 5;
    load_tile(0, OFF_A0, OFF_B0);

    for (int kt = 0; kt < NK; kt++) {
        if (kt + 1 < NK)
            load_tile((kt + 1) << 5, (kt & 1) ? OFF_A0 : OFF_A1,
                                     (kt & 1) ? OFF_B0 : OFF_B1);
        if (kt + 1 < NK) { CP_WAIT(1); } else { CP_WAIT(0); }
        __syncthreads();

        const float* As = smemf + ((kt & 1) ? OFF_A1 : OFF_A0) / 4;
        const float* Bs = smemf + ((kt & 1) ? OFF_B1 : OFF_B0) / 4;
        const int arow0 = wm * 32 + g;
        const int bcol0 = wn * 64 + g;

#pragma unroll
        for (int ks = 0; ks < 4; ks++) {
            const int k0 = ks << 3;
            uint32_t a[2][4];
#pragma unroll
            for (int mi = 0; mi < 2; mi++) {
                const int r = arow0 + mi * 16;
                a[mi][0] = __float_as_uint(As[(r    ) * A_STRIDE + k0 + t    ]);
                a[mi][1] = __float_as_uint(As[(r + 8) * A_STRIDE + k0 + t    ]);
                a[mi][2] = __float_as_uint(As[(r    ) * A_STRIDE + k0 + t + 4]);
                a[mi][3] = __float_as_uint(As[(r + 8) * A_STRIDE + k0 + t + 4]);
                CVT_TF32(a[mi][0]); CVT_TF32(a[mi][1]);
                CVT_TF32(a[mi][2]); CVT_TF32(a[mi][3]);
            }
            uint32_t b[8][2];
#pragma unroll
            for (int ni = 0; ni < 8; ni++) {
                const int col = bcol0 + ni * 8;
                b[ni][0] = __float_as_uint(Bs[(k0 + t    ) * B_STRIDE + col]);
                b[ni][1] = __float_as_uint(Bs[(k0 + t + 4) * B_STRIDE + col]);
                CVT_TF32(b[ni][0]); CVT_TF32(b[ni][1]);
            }
#pragma unroll
            for (int mi = 0; mi < 2; mi++)
#pragma unroll
                for (int ni = 0; ni < 8; ni++)
                    mma_tf32(acc[mi][ni], a[mi], b[ni]);
        }
        __syncthreads();
    }

    // Epilogue: bias (+ReLU) and store. c0,c1 -> (row, col..col+1); c2,c3 -> row+8
#pragma unroll
    for (int mi = 0; mi < 2; mi++) {
        const int row = m0 + wm * 32 + mi * 16 + g;
#pragma unroll
        for (int ni = 0; ni < 8; ni++) {
            const int col = n0 + wn * 64 + ni * 8 + t * 2;
            const float b0 = bias[col], b1 = bias[col + 1];
            float2 lo = make_float2(acc[mi][ni][0] + b0, acc[mi][ni][1] + b1);
            float2 hi = make_float2(acc[mi][ni][2] + b0, acc[mi][ni][3] + b1);
            if (RELU) {
                lo.x = fmaxf(lo.x, 0.f); lo.y = fmaxf(lo.y, 0.f);
                hi.x = fmaxf(hi.x, 0.f); hi.y = fmaxf(hi.y, 0.f);
            }
            *(float2*)(C + (size_t)row * N + col) = lo;
            *(float2*)(C + (size_t)(row + 8) * N + col) = hi;
        }
    }
}

// ---------------------------------------------------------------------------
// Fused window attention: one block per 64-token window.
// ---------------------------------------------------------------------------
__global__ __launch_bounds__(256, 4)
void window_attn(const float* __restrict__ Q, const float* __restrict__ K,
                 const float* __restrict__ V, float* __restrict__ O)
{
    __shared__ float sA[64 * 33 * 2];
    __shared__ float sS[64 * 65];

    const int tid = threadIdx.x;
    const int w = blockIdx.x;
    const float* Qw = Q + (size_t)w * WSZ * E_DIM;
    const float* Kw = K + (size_t)w * WSZ * E_DIM;
    const float* Vw = V + (size_t)w * WSZ * E_DIM;

    float* Qs = sA;
    float* Ks = sA + 64 * 33;

    const int qb = (tid >> 4) << 2;
    const int nb = (tid & 15) << 2;

    float acc[4][4];
#pragma unroll
    for (int i = 0; i < 4; i++)
#pragma unroll
        for (int j = 0; j < 4; j++) acc[i][j] = 0.f;

    for (int c0 = 0; c0 < E_DIM; c0 += 32) {
        __syncthreads();
        for (int i = tid; i < 512; i += 256) {
            const int r = i >> 3;
            const int c4 = (i & 7) << 2;
            const float4 qv = *(const float4*)(Qw + (size_t)r * E_DIM + c0 + c4);
            const float4 kv = *(const float4*)(Kw + (size_t)r * E_DIM + c0 + c4);
            Qs[r * 33 + c4 + 0] = qv.x; Qs[r * 33 + c4 + 1] = qv.y;
            Qs[r * 33 + c4 + 2] = qv.z; Qs[r * 33 + c4 + 3] = qv.w;
            Ks[r * 33 + c4 + 0] = kv.x; Ks[r * 33 + c4 + 1] = kv.y;
            Ks[r * 33 + c4 + 2] = kv.z; Ks[r * 33 + c4 + 3] = kv.w;
        }
        __syncthreads();
#pragma unroll 8
        for (int c = 0; c < 32; c++) {
            float a[4], b[4];
#pragma unroll
            for (int i = 0; i < 4; i++) a[i] = Qs[(qb + i) * 33 + c];
#pragma unroll
            for (int j = 0; j < 4; j++) b[j] = Ks[(nb + j) * 33 + c];
#pragma unroll
            for (int i = 0; i < 4; i++)
#pragma unroll
                for (int j = 0; j < 4; j++)
                    acc[i][j] = fmaf(a[i], b[j], acc[i][j]);
        }
    }

    const float SCALE = 0.03125f;
#pragma unroll
    for (int i = 0; i < 4; i++)
#pragma unroll
        for (int j = 0; j < 4; j++)
            sS[(qb + i) * 65 + nb + j] = acc[i][j] * SCALE;
    __syncthreads();

    {
        const int row = tid >> 2;
        const int part = (tid & 3) << 4;
        float vb[16];
        float m = -1e30f;
#pragma unroll
        for (int j = 0; j < 16; j++) {
            vb[j] = sS[row * 65 + part + j];
            m = fmaxf(m, vb[j]);
        }
        m = fmaxf(m, __shfl_xor_sync(0xffffffffu, m, 1));
        m = fmaxf(m, __shfl_xor_sync(0xffffffffu, m, 2));
        float s = 0.f;
#pragma unroll
        for (int j = 0; j < 16; j++) { vb[j] = __expf(vb[j] - m); s += vb[j]; }
        s += __shfl_xor_sync(0xffffffffu, s, 1);
        s += __shfl_xor_sync(0xffffffffu, s, 2);
        const float inv = 1.f / s;
#pragma unroll
        for (int j = 0; j < 16; j++) sS[row * 65 + part + j] = vb[j] * inv;
    }
    __syncthreads();

    float* Vs = sA;
    for (int e0 = 0; e0 < E_DIM; e0 += 64) {
        __syncthreads();
        for (int i = tid; i < 1024; i += 256) {
            const int r = i >> 4;
            const int c4 = (i & 15) << 2;
            const float4 vv = *(const float4*)(Vw + (size_t)r * E_DIM + e0 + c4);
            Vs[r * 66 + c4 + 0] = vv.x; Vs[r * 66 + c4 + 1] = vv.y;
            Vs[r * 66 + c4 + 2] = vv.z; Vs[r * 66 + c4 + 3] = vv.w;
        }
        __syncthreads();
        float o[4][4];
#pragma unroll
        for (int i = 0; i < 4; i++)
#pragma unroll
            for (int j = 0; j < 4; j++) o[i][j] = 0.f;
#pragma unroll 16
        for (int k = 0; k < 64; k++) {
            float p[4], vv[4];
#pragma unroll
            for (int i = 0; i < 4; i++) p[i] = sS[(qb + i) * 65 + k];
#pragma unroll
            for (int j = 0; j < 4; j++) vv[j] = Vs[k * 66 + nb + j];
#pragma unroll
            for (int i = 0; i < 4; i++)
#pragma unroll
                for (int j = 0; j < 4; j++)
                    o[i][j] = fmaf(p[i], vv[j], o[i][j]);
        }
#pragma unroll
        for (int i = 0; i < 4; i++) {
            float4 c = make_float4(o[i][0], o[i][1], o[i][2], o[i][3]);
            *(float4*)(O + (size_t)(w * WSZ + qb + i) * E_DIM + e0 + nb) = c;
        }
    }
}

// ---------------------------------------------------------------------------
// out = LayerNorm(A + B) * g + be
// ---------------------------------------------------------------------------
__global__ __launch_bounds__(256)
void add_ln(const float* __restrict__ A, const float* __restrict__ B,
            const float* __restrict__ g, const float* __restrict__ be,
            float* __restrict__ out)
{
    const int row = blockIdx.x;
    const int tid = threadIdx.x;
    const int col = tid << 2;

    const float4 a = *(const float4*)(A + (size_t)row * E_DIM + col);
    const float4 b = *(const float4*)(B + (size_t)row * E_DIM + col);
    float v0 = a.x + b.x, v1 = a.y + b.y, v2 = a.z + b.z, v3 = a.w + b.w;

    float s  = v0 + v1 + v2 + v3;
    float sq = v0 * v0 + v1 * v1 + v2 * v2 + v3 * v3;
#pragma unroll
    for (int o = 16; o > 0; o >>= 1) {
        s  += __shfl_xor_sync(0xffffffffu, s, o);
        sq += __shfl_xor_sync(0xffffffffu, sq, o);
    }
    __shared__ float rs[8], rq[8];
    __shared__ float s_mean, s_rstd;
    if ((tid & 31) == 0) { rs[tid >> 5] = s; rq[tid >> 5] = sq; }
    __syncthreads();
    if (tid == 0) {
        float ts = 0.f, tq = 0.f;
#pragma unroll
        for (int i = 0; i < 8; i++) { ts += rs[i]; tq += rq[i]; }
        const float mean = ts * (1.f / E_DIM);
        const float var = tq * (1.f / E_DIM) - mean * mean;
        s_mean = mean;
        s_rstd = rsqrtf(var + 1e-5f);
    }
    __syncthreads();
    const float mean = s_mean, rstd = s_rstd;

    const float4 gg = *(const float4*)(g + col);
    const float4 bb = *(const float4*)(be + col);
    float4 o4;
    o4.x = (v0 - mean) * rstd * gg.x + bb.x;
    o4.y = (v1 - mean) * rstd * gg.y + bb.y;
    o4.z = (v2 - mean) * rstd * gg.z + bb.z;
    o4.w = (v3 - mean) * rstd * gg.w + bb.w;
    *(float4*)(out + (size_t)row * E_DIM + col) = o4;
}

// ---------------------------------------------------------------------------
extern "C" void kernel_launch(void* const* d_in, const int* in_sizes, int n_in,
                              void* d_out, int out_size)
{
    const float* x   = (const float*)d_in[0];
    const float* Wq  = (const float*)d_in[1];
    const float* bq  = (const float*)d_in[2];
    const float* Wk  = (const float*)d_in[3];
    const float* bk  = (const float*)d_in[4];
    const float* Wv  = (const float*)d_in[5];
    const float* bv  = (const float*)d_in[6];
    const float* g1  = (const float*)d_in[7];
    const float* be1 = (const float*)d_in[8];
    const float* W1  = (const float*)d_in[9];
    const float* b1  = (const float*)d_in[10];
    const float* W2  = (const float*)d_in[11];
    const float* b2  = (const float*)d_in[12];
    const float* g2  = (const float*)d_in[13];
    const float* be2 = (const float*)d_in[14];
    float* out = (float*)d_out;

    const int M = in_sizes[0] / E_DIM;   // 16384

    float *Qp, *Kp, *Vp, *Ap, *X1p, *Hp, *Fp;
    cudaGetSymbolAddress((void**)&Qp,  g_Q);
    cudaGetSymbolAddress((void**)&Kp,  g_K);
    cudaGetSymbolAddress((void**)&Vp,  g_V);
    cudaGetSymbolAddress((void**)&Ap,  g_AT);
    cudaGetSymbolAddress((void**)&X1p, g_X1);
    cudaGetSymbolAddress((void**)&Hp,  g_H);
    cudaGetSymbolAddress((void**)&Fp,  g_F);

    cudaFuncSetAttribute(gemm_tf32<0>, cudaFuncAttributeMaxDynamicSharedMemorySize, GEMM_SMEM_BYTES);
    cudaFuncSetAttribute(gemm_tf32<1>, cudaFuncAttributeMaxDynamicSharedMemorySize, GEMM_SMEM_BYTES);

    const dim3 blk(256);
    gemm_tf32<0><<<dim3(E_DIM / 128, M / 128), blk, GEMM_SMEM_BYTES>>>(x, Wq, bq, Qp, M, E_DIM, E_DIM);
    gemm_tf32<0><<<dim3(E_DIM / 128, M / 128), blk, GEMM_SMEM_BYTES>>>(x, Wk, bk, Kp, M, E_DIM, E_DIM);
    gemm_tf32<0><<<dim3(E_DIM / 128, M / 128), blk, GEMM_SMEM_BYTES>>>(x, Wv, bv, Vp, M, E_DIM, E_DIM);

    window_attn<<<M / WSZ, blk>>>(Qp, Kp, Vp, Ap);
    add_ln<<<M, blk>>>(x, Ap, g1, be1, X1p);

    gemm_tf32<1><<<dim3(HID_DIM / 128, M / 128), blk, GEMM_SMEM_BYTES>>>(X1p, W1, b1, Hp, M, HID_DIM, E_DIM);
    gemm_tf32<0><<<dim3(E_DIM / 128, M / 128), blk, GEMM_SMEM_BYTES>>>(Hp, W2, b2, Fp, M, E_DIM, HID_DIM);

    add_ln<<<M, blk>>>(X1p, Fp, g2, be2, out);
}